// round 16
// baseline (speedup 1.0000x reference)
#include <cuda_runtime.h>

// RegionPartitioner, band-aligned write-once: LDG.128 x2 loads + STG.256
// evict-first stores.
// out[b, r, c, i, j] = x[b, c, min(ri*32+i, 499), min(rj*32+j, 499)],
//   r = ri*15 + rj, 15x15 regions of 64x64, step 32.
// Output: (8, 225, 4, 64, 64) fp32.
//
// One thread owns a 32B chunk (8 floats) of ONE row of a 32x32 input band:
// 2 independent LDG.128 (input rows are only 16B-aligned: W=500 floats =
// 2000B, 2000%32=16 -> v8 loads trap; v8 STORES are safe since region-row
// bases are 256B-aligned and jjs is a multiple of 8 floats = 32B) + up to
// 4 STG.256 evict-first. Every output element written exactly once; edge
// replication via load-time clamping. Warp = one (row-band, col-band):
// store bounds warp-uniform; each STG.256 wavefront makes dense 128B runs.

namespace {
constexpr int B  = 8;
constexpr int C  = 4;
constexpr int H  = 500;
constexpr int W  = 500;
constexpr int RS = 64;
constexpr int NR = 15;
constexpr int R  = NR * NR;     // 225
}  // namespace

__device__ __forceinline__ void stg256_cs(float* p, const float* v) {
    asm volatile("st.global.cs.v8.f32 [%0], {%1,%2,%3,%4,%5,%6,%7,%8};"
                 :: "l"(p),
                    "f"(v[0]), "f"(v[1]), "f"(v[2]), "f"(v[3]),
                    "f"(v[4]), "f"(v[5]), "f"(v[6]), "f"(v[7])
                 : "memory");
}

__global__ __launch_bounds__(256)
void region_partition_kernel(const float* __restrict__ x,
                             float* __restrict__ out) {
    const int blk = blockIdx.x;            // 0..127
    const int rbp = blk >> 4;              // row-band pair 0..7
    const int cb  = blk & 15;              // col band 0..15
    const int bc  = blockIdx.y;            // 0..31
    const int b   = bc >> 2;
    const int c   = bc & 3;

    const int t   = threadIdx.x;           // 0..255
    const int rb  = (rbp << 1) | (t >> 7); // row band 0..15; warp-uniform
    const int th  = t & 127;               // thread within band
    const int tg  = th & 3;                // 32B chunk (4 x 32B = 32 cols)
    const int tr  = th >> 2;               // row within band 0..31

    // ---- Load this thread's 32B chunk once (clamped at edges). ----
    const int row  = min(rb * 32 + tr, H - 1);   // rb==15, tr>=20 -> 499
    const int col0 = cb * 32 + tg * 8;
    const float* src = x + ((long long)bc * H + row) * W;

    float v[8];
    if (col0 + 7 <= W - 1) {
        // Two independent LDG.128 (16B alignment guaranteed; MLP=2).
        float4 a0 = *reinterpret_cast<const float4*>(src + col0);
        float4 a1 = *reinterpret_cast<const float4*>(src + col0 + 4);
        v[0] = a0.x; v[1] = a0.y; v[2] = a0.z; v[3] = a0.w;
        v[4] = a1.x; v[5] = a1.y; v[6] = a1.z; v[7] = a1.w;
    } else {                               // cb==15, tg>=2: cols >= 496
#pragma unroll
        for (int q = 0; q < 8; q++) v[q] = src[min(col0 + q, W - 1)];
    }

    // ---- Target regions (warp-uniform branches). ----
    int ris[2], iis[2], nri = 0;
    if (rb >= 1)      { ris[nri] = rb - 1; iis[nri] = 32 + tr;     nri++; }
    if (rb <= NR - 1) { ris[nri] = rb;     iis[nri] = tr;          nri++; }
    int rjs[2], jjs[2], nrj = 0;
    if (cb >= 1)      { rjs[nrj] = cb - 1; jjs[nrj] = 32 + 8 * tg; nrj++; }
    if (cb <= NR - 1) { rjs[nrj] = cb;     jjs[nrj] = 8 * tg;      nrj++; }

    // Stores: per (a,d) one STG.256; 4 consecutive tg -> contiguous 128B run.
#pragma unroll
    for (int a = 0; a < 2; a++) {
        if (a >= nri) break;
#pragma unroll
        for (int d = 0; d < 2; d++) {
            if (d >= nrj) break;
            float* dst = out +
                (((long long)(b * R + ris[a] * NR + rjs[d]) * C + c) * RS +
                 iis[a]) * RS + jjs[d];
            stg256_cs(dst, v);             // 32B-aligned (see header comment)
        }
    }
}

extern "C" void kernel_launch(void* const* d_in, const int* in_sizes, int n_in,
                              void* d_out, int out_size) {
    const float* x = (const float*)d_in[0];
    float* out = (float*)d_out;

    dim3 grid(8 * 16, B * C);   // (128, 32) = 4096 blocks, 1.05M threads
    region_partition_kernel<<<grid, 256>>>(x, out);
}